// round 4
// baseline (speedup 1.0000x reference)
#include <cuda_runtime.h>
#include <math.h>
#include <stdint.h>

#define BB  2
#define SSL 2048
#define DD  1024
#define HH  16
#define HDD 64
#define MSZ (BB*SSL)

// Scratch (allocation-free rule: device globals)
__device__ float g_q[MSZ*DD];
__device__ float g_kt[MSZ*DD];   // raw K after proj, softplus(K) after fuse
__device__ float g_v[MSZ*DD];

// ---------------------------------------------------------------------------
// tf32 helpers
// ---------------------------------------------------------------------------
__device__ __forceinline__ uint32_t f2tf32(float x) {
    uint32_t r;
    asm("cvt.rna.tf32.f32 %0, %1;" : "=r"(r) : "f"(x));
    return r;
}

__device__ __forceinline__ void mma_tf32(float c[4], const uint32_t a[4],
                                         uint32_t b0, uint32_t b1) {
    asm volatile(
        "mma.sync.aligned.m16n8k8.row.col.f32.tf32.tf32.f32 "
        "{%0,%1,%2,%3}, {%4,%5,%6,%7}, {%8,%9}, {%0,%1,%2,%3};"
        : "+f"(c[0]), "+f"(c[1]), "+f"(c[2]), "+f"(c[3])
        : "r"(a[0]), "r"(a[1]), "r"(a[2]), "r"(a[3]), "r"(b0), "r"(b1));
}

// ---------------------------------------------------------------------------
// Projection GEMM (tf32, double-buffered smem, 1 sync per k-tile)
// CTA 128x128, k-tile 32, 8 warps 4m x 2n, warp tile 32x64.
// ---------------------------------------------------------------------------
#define XS_STR 36
#define WS_STR 136
#define XS_BUF (128*XS_STR)
#define WS_BUF (32*WS_STR)
#define PROJ_SMEM ((2*XS_BUF + 2*WS_BUF)*4)

__global__ void __launch_bounds__(256, 2) proj_tc(
    const float* __restrict__ X,
    const float* __restrict__ Wq, const float* __restrict__ bq,
    const float* __restrict__ Wk, const float* __restrict__ bk)
{
    const float* W   = (blockIdx.z == 0) ? Wq : Wk;
    const float* bia = (blockIdx.z == 0) ? bq : bk;
    float*       outp= (blockIdx.z == 0) ? g_q : g_kt;

    extern __shared__ uint32_t psm[];
    uint32_t* XsB = psm;                 // [2][XS_BUF]
    uint32_t* WsB = psm + 2*XS_BUF;      // [2][WS_BUF]

    const int m0 = blockIdx.y * 128;
    const int n0 = blockIdx.x * 128;
    const int t    = threadIdx.x;
    const int warp = t >> 5;
    const int lane = t & 31;
    const int lq   = lane & 3;
    const int lr   = lane >> 2;
    const int wm = (warp >> 1) * 32;
    const int wn = (warp & 1) * 64;

    const int xr = t >> 1;          // 0..127
    const int xcb = (t & 1) * 4;    // float4 col base
    const int wr = t >> 3;          // 0..31
    const int wcb = t & 7;

    float acc[2][8][4] = {};

    {   // k-tile 0 -> buffer 0
        const float* xp = X + (size_t)(m0 + xr) * DD;
        #pragma unroll
        for (int j = 0; j < 4; j++) {
            int c = xcb + j;
            float4 f = *(const float4*)(xp + 4*c);
            *(uint4*)&XsB[xr*XS_STR + 4*c] =
                make_uint4(f2tf32(f.x), f2tf32(f.y), f2tf32(f.z), f2tf32(f.w));
        }
        const float* wp = W + (size_t)wr * DD + n0;
        #pragma unroll
        for (int j = 0; j < 4; j++) {
            int c = wcb + 8*j;
            float4 f = *(const float4*)(wp + 4*c);
            *(uint4*)&WsB[wr*WS_STR + 4*c] =
                make_uint4(f2tf32(f.x), f2tf32(f.y), f2tf32(f.z), f2tf32(f.w));
        }
    }
    __syncthreads();

    for (int k0 = 0; k0 < DD; k0 += 32) {
        const int buf = (k0 >> 5) & 1;
        uint32_t* Xs = XsB + buf*XS_BUF;
        uint32_t* Ws = WsB + buf*WS_BUF;
        const bool more = (k0 + 32) < DD;

        float4 xst[4], wst[4];
        if (more) {
            const float* xp = X + (size_t)(m0 + xr) * DD + k0 + 32;
            #pragma unroll
            for (int j = 0; j < 4; j++)
                xst[j] = *(const float4*)(xp + 4*(xcb + j));
            const float* wp = W + (size_t)(k0 + 32 + wr) * DD + n0;
            #pragma unroll
            for (int j = 0; j < 4; j++)
                wst[j] = *(const float4*)(wp + 4*(wcb + 8*j));
        }

        #pragma unroll
        for (int ks = 0; ks < 4; ks++) {
            int kb = ks * 8;
            uint32_t a[2][4];
            #pragma unroll
            for (int mt = 0; mt < 2; mt++) {
                int ar = wm + 16*mt + lr;
                a[mt][0] = Xs[ar*XS_STR + kb + lq];
                a[mt][1] = Xs[(ar+8)*XS_STR + kb + lq];
                a[mt][2] = Xs[ar*XS_STR + kb + lq + 4];
                a[mt][3] = Xs[(ar+8)*XS_STR + kb + lq + 4];
            }
            #pragma unroll
            for (int nt = 0; nt < 8; nt++) {
                int bc = wn + 8*nt + lr;
                uint32_t b0 = Ws[(kb + lq)*WS_STR + bc];
                uint32_t b1 = Ws[(kb + 4 + lq)*WS_STR + bc];
                mma_tf32(acc[0][nt], a[0], b0, b1);
                mma_tf32(acc[1][nt], a[1], b0, b1);
            }
        }

        if (more) {
            uint32_t* Xn = XsB + (buf^1)*XS_BUF;
            uint32_t* Wn = WsB + (buf^1)*WS_BUF;
            #pragma unroll
            for (int j = 0; j < 4; j++) {
                float4 f = xst[j];
                *(uint4*)&Xn[xr*XS_STR + 4*(xcb + j)] =
                    make_uint4(f2tf32(f.x), f2tf32(f.y), f2tf32(f.z), f2tf32(f.w));
            }
            #pragma unroll
            for (int j = 0; j < 4; j++) {
                float4 f = wst[j];
                *(uint4*)&Wn[wr*WS_STR + 4*(wcb + 8*j)] =
                    make_uint4(f2tf32(f.x), f2tf32(f.y), f2tf32(f.z), f2tf32(f.w));
            }
        }
        __syncthreads();
    }

    #pragma unroll
    for (int nt = 0; nt < 8; nt++) {
        int c = n0 + wn + 8*nt + 2*lq;
        float bx = bia[c], by = bia[c+1];
        #pragma unroll
        for (int mt = 0; mt < 2; mt++) {
            int r = m0 + wm + 16*mt + lr;
            *(float2*)(outp + (size_t)r * DD + c) =
                make_float2(acc[mt][nt][0] + bx, acc[mt][nt][1] + by);
            *(float2*)(outp + (size_t)(r+8) * DD + c) =
                make_float2(acc[mt][nt][2] + bx, acc[mt][nt][3] + by);
        }
    }
}

// ---------------------------------------------------------------------------
// Elementwise: kt = softplus(k_raw), v = q + k_raw
// ---------------------------------------------------------------------------
__device__ __forceinline__ float softplus_f(float x) {
    return (x > 15.0f) ? x : log1pf(__expf(x));
}

__global__ __launch_bounds__(256) void fuse_kernel()
{
    int i = blockIdx.x * 256 + threadIdx.x;
    float4 q = ((const float4*)g_q)[i];
    float4 k = ((const float4*)g_kt)[i];
    float4 v, kt;
    v.x = q.x + k.x;  v.y = q.y + k.y;  v.z = q.z + k.z;  v.w = q.w + k.w;
    kt.x = softplus_f(k.x);
    kt.y = softplus_f(k.y);
    kt.z = softplus_f(k.z);
    kt.w = softplus_f(k.w);
    ((float4*)g_v)[i]  = v;
    ((float4*)g_kt)[i] = kt;
}

// ---------------------------------------------------------------------------
// Flash attention, tf32, register-resident online softmax.
// CTA = 128 threads (4 warps); warp w owns query rows 16w..16w+15 fully
// (all 64 keys, all 64 dims). 2 __syncthreads per key tile.
// Query-axis mask -> row -10000 (uniform softmax, matches reference).
// ---------------------------------------------------------------------------
#define QS_STR 68
#define KT_STR 72
#define VS_STR 72
#define PS_STR 68
#define SMEM_ATTN ((64*QS_STR + 64*KT_STR + 64*VS_STR + 64*PS_STR)*4)

__global__ void __launch_bounds__(128, 3) attn_tc(
    const int* __restrict__ amask, float* __restrict__ out)
{
    extern __shared__ uint32_t smu[];
    uint32_t* Qs  = smu;               // [64][QS_STR] q-major, tf32 (pre-scaled 1/8)
    uint32_t* KsT = Qs  + 64*QS_STR;   // [64][KT_STR] d-major
    uint32_t* Vs  = KsT + 64*KT_STR;   // [64][VS_STR] key-major
    uint32_t* Ps  = Vs  + 64*VS_STR;   // [64][PS_STR] q-major probs (tf32)

    const int qt = blockIdx.x, h = blockIdx.y, b = blockIdx.z;
    const int t    = threadIdx.x;
    const int warp = t >> 5;
    const int lane = t & 31;
    const int lq   = lane & 3;
    const int lr   = lane >> 2;
    const int r0 = warp*16 + lr, r1 = r0 + 8;
    const int lrow = t >> 1, lv = t & 1;

    {   // Q tile -> smem (tf32, 1/8 folded)
        const float* qp = g_q + ((size_t)(b*SSL + qt*64 + lrow))*DD + h*HDD;
        #pragma unroll
        for (int j = 0; j < 8; j++) {
            int c = 8*lv + j;
            float4 f = *(const float4*)(qp + 4*c);
            *(uint4*)&Qs[lrow*QS_STR + 4*c] =
                make_uint4(f2tf32(f.x*0.125f), f2tf32(f.y*0.125f),
                           f2tf32(f.z*0.125f), f2tf32(f.w*0.125f));
        }
    }
    {   // K/V tile 0
        size_t base = ((size_t)(b*SSL + lrow))*DD + h*HDD;
        #pragma unroll
        for (int j = 0; j < 8; j++) {
            int c = 8*lv + j;
            float4 kf = *(const float4*)(g_kt + base + 4*c);
            KsT[(4*c+0)*KT_STR + lrow] = f2tf32(kf.x);
            KsT[(4*c+1)*KT_STR + lrow] = f2tf32(kf.y);
            KsT[(4*c+2)*KT_STR + lrow] = f2tf32(kf.z);
            KsT[(4*c+3)*KT_STR + lrow] = f2tf32(kf.w);
            float4 vf = *(const float4*)(g_v + base + 4*c);
            *(uint4*)&Vs[lrow*VS_STR + 4*c] =
                make_uint4(f2tf32(vf.x), f2tf32(vf.y), f2tf32(vf.z), f2tf32(vf.w));
        }
    }
    const bool m0f = (amask[b*SSL + qt*64 + r0] == 0);
    const bool m1f = (amask[b*SSL + qt*64 + r1] == 0);

    float mm0 = -1e30f, mm1 = -1e30f, l0 = 0.0f, l1 = 0.0f;
    float accO[8][4] = {};
    __syncthreads();

    for (int k0 = 0; k0 < SSL; k0 += 64) {
        // ---- S = (Q/8) @ K^T : warp computes 16x64 ----
        float accS[8][4] = {};
        #pragma unroll
        for (int ks = 0; ks < 8; ks++) {
            int kb = ks * 8;
            uint32_t a[4];
            a[0] = Qs[r0*QS_STR + kb + lq];
            a[1] = Qs[r1*QS_STR + kb + lq];
            a[2] = Qs[r0*QS_STR + kb + 4 + lq];
            a[3] = Qs[r1*QS_STR + kb + 4 + lq];
            #pragma unroll
            for (int nt = 0; nt < 8; nt++) {
                int bc = 8*nt + lr;
                mma_tf32(accS[nt], a,
                         KsT[(kb + lq)*KT_STR + bc],
                         KsT[(kb + 4 + lq)*KT_STR + bc]);
            }
        }

        // ---- online softmax, registers only ----
        float mx0 = -1e30f, mx1 = -1e30f;
        #pragma unroll
        for (int nt = 0; nt < 8; nt++) {
            mx0 = fmaxf(mx0, fmaxf(accS[nt][0], accS[nt][1]));
            mx1 = fmaxf(mx1, fmaxf(accS[nt][2], accS[nt][3]));
        }
        if (m0f) mx0 = -10000.0f;
        if (m1f) mx1 = -10000.0f;
        mx0 = fmaxf(mx0, __shfl_xor_sync(0xffffffffu, mx0, 1));
        mx0 = fmaxf(mx0, __shfl_xor_sync(0xffffffffu, mx0, 2));
        mx1 = fmaxf(mx1, __shfl_xor_sync(0xffffffffu, mx1, 1));
        mx1 = fmaxf(mx1, __shfl_xor_sync(0xffffffffu, mx1, 2));
        float mn0 = fmaxf(mm0, mx0), mn1 = fmaxf(mm1, mx1);
        float c0 = __expf(mm0 - mn0), c1 = __expf(mm1 - mn1);
        mm0 = mn0; mm1 = mn1;
        float s0 = 0.0f, s1 = 0.0f;
        #pragma unroll
        for (int nt = 0; nt < 8; nt++) {
            float p00 = __expf((m0f ? -10000.0f : accS[nt][0]) - mn0);
            float p01 = __expf((m0f ? -10000.0f : accS[nt][1]) - mn0);
            float p10 = __expf((m1f ? -10000.0f : accS[nt][2]) - mn1);
            float p11 = __expf((m1f ? -10000.0f : accS[nt][3]) - mn1);
            s0 += p00 + p01;
            s1 += p10 + p11;
            *(uint2*)&Ps[r0*PS_STR + 8*nt + 2*lq] = make_uint2(f2tf32(p00), f2tf32(p01));
            *(uint2*)&Ps[r1*PS_STR + 8*nt + 2*lq] = make_uint2(f2tf32(p10), f2tf32(p11));
        }
        s0 += __shfl_xor_sync(0xffffffffu, s0, 1);
        s0 += __shfl_xor_sync(0xffffffffu, s0, 2);
        s1 += __shfl_xor_sync(0xffffffffu, s1, 1);
        s1 += __shfl_xor_sync(0xffffffffu, s1, 2);
        l0 = l0 * c0 + s0;
        l1 = l1 * c1 + s1;
        #pragma unroll
        for (int nt = 0; nt < 8; nt++) {
            accO[nt][0] *= c0; accO[nt][1] *= c0;
            accO[nt][2] *= c1; accO[nt][3] *= c1;
        }
        __syncwarp();   // Ps visible within warp

        // ---- O += P @ V ----
        #pragma unroll
        for (int ks = 0; ks < 8; ks++) {
            int kb = ks * 8;
            uint32_t a[4];
            a[0] = Ps[r0*PS_STR + kb + lq];
            a[1] = Ps[r1*PS_STR + kb + lq];
            a[2] = Ps[r0*PS_STR + kb + 4 + lq];
            a[3] = Ps[r1*PS_STR + kb + 4 + lq];
            #pragma unroll
            for (int nt = 0; nt < 8; nt++) {
                int bc = 8*nt + lr;
                mma_tf32(accO[nt], a,
                         Vs[(kb + lq)*VS_STR + bc],
                         Vs[(kb + 4 + lq)*VS_STR + bc]);
            }
        }
        __syncthreads();   // everyone done reading KsT/Vs

        if (k0 + 64 < SSL) {   // next K/V tile
            size_t base = ((size_t)(b*SSL + k0 + 64 + lrow))*DD + h*HDD;
            #pragma unroll
            for (int j = 0; j < 8; j++) {
                int c = 8*lv + j;
                float4 kf = *(const float4*)(g_kt + base + 4*c);
                KsT[(4*c+0)*KT_STR + lrow] = f2tf32(kf.x);
                KsT[(4*c+1)*KT_STR + lrow] = f2tf32(kf.y);
                KsT[(4*c+2)*KT_STR + lrow] = f2tf32(kf.z);
                KsT[(4*c+3)*KT_STR + lrow] = f2tf32(kf.w);
                float4 vf = *(const float4*)(g_v + base + 4*c);
                *(uint4*)&Vs[lrow*VS_STR + 4*c] =
                    make_uint4(f2tf32(vf.x), f2tf32(vf.y), f2tf32(vf.z), f2tf32(vf.w));
            }
        }
        __syncthreads();   // new tile visible
    }

    // ---- epilogue: O / l ----
    {
        float li0 = 1.0f / l0, li1 = 1.0f / l1;
        size_t row0 = (size_t)(b*SSL + qt*64 + r0) * DD + h*HDD;
        size_t row1 = (size_t)(b*SSL + qt*64 + r1) * DD + h*HDD;
        #pragma unroll
        for (int nt = 0; nt < 8; nt++) {
            int col = 8*nt + 2*lq;
            *(float2*)(out + row0 + col) = make_float2(accO[nt][0]*li0, accO[nt][1]*li0);
            *(float2*)(out + row1 + col) = make_float2(accO[nt][2]*li1, accO[nt][3]*li1);
        }
    }
}

// ---------------------------------------------------------------------------
extern "C" void kernel_launch(void* const* d_in, const int* in_sizes, int n_in,
                              void* d_out, int out_size)
{
    const float* X     = (const float*)d_in[0];
    const int*   amask = (const int*)  d_in[1];
    const float* Wq    = (const float*)d_in[2];
    const float* bq    = (const float*)d_in[3];
    const float* Wk    = (const float*)d_in[4];
    const float* bk    = (const float*)d_in[5];
    float*       out   = (float*)d_out;

    cudaFuncSetAttribute(proj_tc,
                         cudaFuncAttributeMaxDynamicSharedMemorySize, PROJ_SMEM);
    cudaFuncSetAttribute(attn_tc,
                         cudaFuncAttributeMaxDynamicSharedMemorySize, SMEM_ATTN);

    proj_tc<<<dim3(DD/128, MSZ/128, 2), 256, PROJ_SMEM>>>(X, Wq, bq, Wk, bk);
    fuse_kernel<<<(MSZ*DD/4)/256, 256>>>();
    attn_tc<<<dim3(SSL/64, HH, BB), 128, SMEM_ATTN>>>(amask, out);
}

// round 5
// speedup vs baseline: 1.4062x; 1.4062x over previous
#include <cuda_runtime.h>
#include <math.h>
#include <stdint.h>

#define BB  2
#define SSL 2048
#define DD  1024
#define HH  16
#define HDD 64
#define MSZ (BB*SSL)

// Scratch (allocation-free rule: device globals)
__device__ float g_q[MSZ*DD];
__device__ float g_kt[MSZ*DD];   // softplus(K)
__device__ float g_v[MSZ*DD];    // Q + K

// ---------------------------------------------------------------------------
// tf32 helpers
// ---------------------------------------------------------------------------
__device__ __forceinline__ uint32_t f2tf32(float x) {
    uint32_t r;
    asm("cvt.rna.tf32.f32 %0, %1;" : "=r"(r) : "f"(x));
    return r;
}

__device__ __forceinline__ void mma_tf32(float c[4], const uint32_t a[4],
                                         uint32_t b0, uint32_t b1) {
    asm volatile(
        "mma.sync.aligned.m16n8k8.row.col.f32.tf32.tf32.f32 "
        "{%0,%1,%2,%3}, {%4,%5,%6,%7}, {%8,%9}, {%0,%1,%2,%3};"
        : "+f"(c[0]), "+f"(c[1]), "+f"(c[2]), "+f"(c[3])
        : "r"(a[0]), "r"(a[1]), "r"(a[2]), "r"(a[3]), "r"(b0), "r"(b1));
}

__device__ __forceinline__ float softplus_f(float x) {
    return (x > 15.0f) ? x : log1pf(__expf(x));
}

// ---------------------------------------------------------------------------
// Fused projection: computes Q = X@Wq+bq and K = X@Wk+bk on the SAME tile
// (shared X), epilogue writes g_q = Q, g_kt = softplus(K), g_v = Q + K.
// CTA: 128m x 64n, k-tile 32, double-buffered smem, 8 warps 4m x 2n.
// ---------------------------------------------------------------------------
#define XS_STR 36
#define WS_STR 72
#define XS_BUF (128*XS_STR)
#define WS_BUF (32*WS_STR)
#define PROJ_SMEM ((2*XS_BUF + 4*WS_BUF)*4)

__global__ void __launch_bounds__(256, 2) proj_tc(
    const float* __restrict__ X,
    const float* __restrict__ Wq, const float* __restrict__ bq,
    const float* __restrict__ Wk, const float* __restrict__ bk)
{
    extern __shared__ uint32_t psm[];
    uint32_t* XsB  = psm;                       // [2][XS_BUF]
    uint32_t* WqsB = psm + 2*XS_BUF;            // [2][WS_BUF]
    uint32_t* WksB = WqsB + 2*WS_BUF;           // [2][WS_BUF]

    const int m0 = blockIdx.y * 128;
    const int n0 = blockIdx.x * 64;
    const int t    = threadIdx.x;
    const int warp = t >> 5;
    const int lane = t & 31;
    const int lq   = lane & 3;
    const int lr   = lane >> 2;
    const int wm = (warp >> 1) * 32;
    const int wn = (warp & 1) * 32;

    const int xr = t >> 1;          // 0..127
    const int xcb = (t & 1) * 4;    // float4 col base (8 cols of float4)
    const int wr = t >> 3;          // 0..31
    const int wcb = t & 7;          // float4 col: wcb, wcb+8 (16 cols)

    float accq[2][4][4] = {};
    float acck[2][4][4] = {};

    {   // k-tile 0 -> buffer 0
        const float* xp = X + (size_t)(m0 + xr) * DD;
        #pragma unroll
        for (int j = 0; j < 4; j++) {
            int c = xcb + j;
            float4 f = *(const float4*)(xp + 4*c);
            *(uint4*)&XsB[xr*XS_STR + 4*c] =
                make_uint4(f2tf32(f.x), f2tf32(f.y), f2tf32(f.z), f2tf32(f.w));
        }
        const float* wqp = Wq + (size_t)wr * DD + n0;
        const float* wkp = Wk + (size_t)wr * DD + n0;
        #pragma unroll
        for (int j = 0; j < 2; j++) {
            int c = wcb + 8*j;
            float4 fq = *(const float4*)(wqp + 4*c);
            *(uint4*)&WqsB[wr*WS_STR + 4*c] =
                make_uint4(f2tf32(fq.x), f2tf32(fq.y), f2tf32(fq.z), f2tf32(fq.w));
            float4 fk = *(const float4*)(wkp + 4*c);
            *(uint4*)&WksB[wr*WS_STR + 4*c] =
                make_uint4(f2tf32(fk.x), f2tf32(fk.y), f2tf32(fk.z), f2tf32(fk.w));
        }
    }
    __syncthreads();

    for (int k0 = 0; k0 < DD; k0 += 32) {
        const int buf = (k0 >> 5) & 1;
        uint32_t* Xs  = XsB  + buf*XS_BUF;
        uint32_t* Wqs = WqsB + buf*WS_BUF;
        uint32_t* Wks = WksB + buf*WS_BUF;
        const bool more = (k0 + 32) < DD;

        float4 xst[4], wqst[2], wkst[2];
        if (more) {
            const float* xp = X + (size_t)(m0 + xr) * DD + k0 + 32;
            #pragma unroll
            for (int j = 0; j < 4; j++)
                xst[j] = *(const float4*)(xp + 4*(xcb + j));
            const float* wqp = Wq + (size_t)(k0 + 32 + wr) * DD + n0;
            const float* wkp = Wk + (size_t)(k0 + 32 + wr) * DD + n0;
            #pragma unroll
            for (int j = 0; j < 2; j++) {
                wqst[j] = *(const float4*)(wqp + 4*(wcb + 8*j));
                wkst[j] = *(const float4*)(wkp + 4*(wcb + 8*j));
            }
        }

        #pragma unroll
        for (int ks = 0; ks < 4; ks++) {
            int kb = ks * 8;
            uint32_t a[2][4];
            #pragma unroll
            for (int mt = 0; mt < 2; mt++) {
                int ar = wm + 16*mt + lr;
                a[mt][0] = Xs[ar*XS_STR + kb + lq];
                a[mt][1] = Xs[(ar+8)*XS_STR + kb + lq];
                a[mt][2] = Xs[ar*XS_STR + kb + lq + 4];
                a[mt][3] = Xs[(ar+8)*XS_STR + kb + lq + 4];
            }
            #pragma unroll
            for (int nt = 0; nt < 4; nt++) {
                int bc = wn + 8*nt + lr;
                uint32_t q0 = Wqs[(kb + lq)*WS_STR + bc];
                uint32_t q1 = Wqs[(kb + 4 + lq)*WS_STR + bc];
                uint32_t k0r = Wks[(kb + lq)*WS_STR + bc];
                uint32_t k1r = Wks[(kb + 4 + lq)*WS_STR + bc];
                #pragma unroll
                for (int mt = 0; mt < 2; mt++) {
                    mma_tf32(accq[mt][nt], a[mt], q0, q1);
                    mma_tf32(acck[mt][nt], a[mt], k0r, k1r);
                }
            }
        }

        if (more) {
            uint32_t* Xn  = XsB  + (buf^1)*XS_BUF;
            uint32_t* Wqn = WqsB + (buf^1)*WS_BUF;
            uint32_t* Wkn = WksB + (buf^1)*WS_BUF;
            #pragma unroll
            for (int j = 0; j < 4; j++) {
                float4 f = xst[j];
                *(uint4*)&Xn[xr*XS_STR + 4*(xcb + j)] =
                    make_uint4(f2tf32(f.x), f2tf32(f.y), f2tf32(f.z), f2tf32(f.w));
            }
            #pragma unroll
            for (int j = 0; j < 2; j++) {
                float4 fq = wqst[j];
                *(uint4*)&Wqn[wr*WS_STR + 4*(wcb + 8*j)] =
                    make_uint4(f2tf32(fq.x), f2tf32(fq.y), f2tf32(fq.z), f2tf32(fq.w));
                float4 fk = wkst[j];
                *(uint4*)&Wkn[wr*WS_STR + 4*(wcb + 8*j)] =
                    make_uint4(f2tf32(fk.x), f2tf32(fk.y), f2tf32(fk.z), f2tf32(fk.w));
            }
        }
        __syncthreads();
    }

    // epilogue: q = accq+bq, k = acck+bk; g_q=q, g_kt=softplus(k), g_v=q+k
    #pragma unroll
    for (int nt = 0; nt < 4; nt++) {
        int c = n0 + wn + 8*nt + 2*lq;
        float bqx = bq[c], bqy = bq[c+1];
        float bkx = bk[c], bky = bk[c+1];
        #pragma unroll
        for (int mt = 0; mt < 2; mt++) {
            #pragma unroll
            for (int half = 0; half < 2; half++) {
                int r = m0 + wm + 16*mt + lr + 8*half;
                float qx = accq[mt][nt][2*half+0] + bqx;
                float qy = accq[mt][nt][2*half+1] + bqy;
                float kx = acck[mt][nt][2*half+0] + bkx;
                float ky = acck[mt][nt][2*half+1] + bky;
                size_t off = (size_t)r * DD + c;
                *(float2*)(g_q  + off) = make_float2(qx, qy);
                *(float2*)(g_kt + off) = make_float2(softplus_f(kx), softplus_f(ky));
                *(float2*)(g_v  + off) = make_float2(qx + kx, qy + ky);
            }
        }
    }
}

// ---------------------------------------------------------------------------
// Flash attention, tf32, register-resident online softmax.
// CTA = 256 threads (8 warps), Q-tile 128 queries; warp w owns rows
// 16w..16w+15. Key tiles of 64, K/V stored KEY-MAJOR (no transpose; the
// row.col B-fragment reads K[key][dim] directly).
// Query-axis mask -> row -10000 (uniform softmax, matches reference).
// ---------------------------------------------------------------------------
#define AQ_STR 68    // Qs [128][68] q-major   (banks 4lr+lq on A reads)
#define AK_STR 68    // Ks [64][68]  key-major (banks 4lr+lq on B reads)
#define AV_STR 72    // Vs [64][72]  key-major (banks 8lq+lr on B reads)
#define AP_STR 68    // Ps [128][68] q-major
#define SMEM_ATTN ((128*AQ_STR + 64*AK_STR + 64*AV_STR + 128*AP_STR)*4)

__global__ void __launch_bounds__(256, 2) attn_tc(
    const int* __restrict__ amask, float* __restrict__ out)
{
    extern __shared__ uint32_t smu[];
    uint32_t* Qs = smu;                // [128][AQ_STR]
    uint32_t* Ks = Qs + 128*AQ_STR;    // [64][AK_STR]
    uint32_t* Vs = Ks + 64*AK_STR;     // [64][AV_STR]
    uint32_t* Ps = Vs + 64*AV_STR;     // [128][AP_STR]

    const int qt = blockIdx.x, h = blockIdx.y, b = blockIdx.z;
    const int t    = threadIdx.x;
    const int warp = t >> 5;
    const int lane = t & 31;
    const int lq   = lane & 3;
    const int lr   = lane >> 2;
    const int r0 = warp*16 + lr, r1 = r0 + 8;
    const int qrow = t >> 1, qv = t & 1;    // Q loader: 128 rows x 2 threads
    const int krow = t >> 2, kv = t & 3;    // K/V loader: 64 rows x 4 threads

    {   // Q tile -> smem (tf32, 1/8 folded)
        const float* qp = g_q + ((size_t)(b*SSL + qt*128 + qrow))*DD + h*HDD;
        #pragma unroll
        for (int j = 0; j < 8; j++) {
            int c = 8*qv + j;
            float4 f = *(const float4*)(qp + 4*c);
            *(uint4*)&Qs[qrow*AQ_STR + 4*c] =
                make_uint4(f2tf32(f.x*0.125f), f2tf32(f.y*0.125f),
                           f2tf32(f.z*0.125f), f2tf32(f.w*0.125f));
        }
    }
    {   // K/V tile 0 (key-major, straight copy + cvt)
        size_t base = ((size_t)(b*SSL + krow))*DD + h*HDD;
        #pragma unroll
        for (int j = 0; j < 4; j++) {
            int c = kv + 4*j;
            float4 kf = *(const float4*)(g_kt + base + 4*c);
            *(uint4*)&Ks[krow*AK_STR + 4*c] =
                make_uint4(f2tf32(kf.x), f2tf32(kf.y), f2tf32(kf.z), f2tf32(kf.w));
            float4 vf = *(const float4*)(g_v + base + 4*c);
            *(uint4*)&Vs[krow*AV_STR + 4*c] =
                make_uint4(f2tf32(vf.x), f2tf32(vf.y), f2tf32(vf.z), f2tf32(vf.w));
        }
    }
    const bool m0f = (amask[b*SSL + qt*128 + r0] == 0);
    const bool m1f = (amask[b*SSL + qt*128 + r1] == 0);

    float mm0 = -1e30f, mm1 = -1e30f, l0 = 0.0f, l1 = 0.0f;
    float accO[8][4] = {};
    __syncthreads();

    for (int k0 = 0; k0 < SSL; k0 += 64) {
        // ---- S = (Q/8) @ K^T : warp computes 16x64 ----
        float accS[8][4] = {};
        #pragma unroll
        for (int ks = 0; ks < 8; ks++) {
            int kb = ks * 8;
            uint32_t a[4];
            a[0] = Qs[r0*AQ_STR + kb + lq];
            a[1] = Qs[r1*AQ_STR + kb + lq];
            a[2] = Qs[r0*AQ_STR + kb + 4 + lq];
            a[3] = Qs[r1*AQ_STR + kb + 4 + lq];
            #pragma unroll
            for (int nt = 0; nt < 8; nt++) {
                int key0 = 8*nt + lr;
                mma_tf32(accS[nt], a,
                         Ks[key0*AK_STR + kb + lq],
                         Ks[key0*AK_STR + kb + 4 + lq]);
            }
        }

        // ---- online softmax, registers only ----
        float mx0 = -1e30f, mx1 = -1e30f;
        #pragma unroll
        for (int nt = 0; nt < 8; nt++) {
            mx0 = fmaxf(mx0, fmaxf(accS[nt][0], accS[nt][1]));
            mx1 = fmaxf(mx1, fmaxf(accS[nt][2], accS[nt][3]));
        }
        if (m0f) mx0 = -10000.0f;
        if (m1f) mx1 = -10000.0f;
        mx0 = fmaxf(mx0, __shfl_xor_sync(0xffffffffu, mx0, 1));
        mx0 = fmaxf(mx0, __shfl_xor_sync(0xffffffffu, mx0, 2));
        mx1 = fmaxf(mx1, __shfl_xor_sync(0xffffffffu, mx1, 1));
        mx1 = fmaxf(mx1, __shfl_xor_sync(0xffffffffu, mx1, 2));
        float mn0 = fmaxf(mm0, mx0), mn1 = fmaxf(mm1, mx1);
        float c0 = __expf(mm0 - mn0), c1 = __expf(mm1 - mn1);
        mm0 = mn0; mm1 = mn1;
        float s0 = 0.0f, s1 = 0.0f;
        #pragma unroll
        for (int nt = 0; nt < 8; nt++) {
            float p00 = __expf((m0f ? -10000.0f : accS[nt][0]) - mn0);
            float p01 = __expf((m0f ? -10000.0f : accS[nt][1]) - mn0);
            float p10 = __expf((m1f ? -10000.0f : accS[nt][2]) - mn1);
            float p11 = __expf((m1f ? -10000.0f : accS[nt][3]) - mn1);
            s0 += p00 + p01;
            s1 += p10 + p11;
            *(uint2*)&Ps[r0*AP_STR + 8*nt + 2*lq] = make_uint2(f2tf32(p00), f2tf32(p01));
            *(uint2*)&Ps[r1*AP_STR + 8*nt + 2*lq] = make_uint2(f2tf32(p10), f2tf32(p11));
        }
        s0 += __shfl_xor_sync(0xffffffffu, s0, 1);
        s0 += __shfl_xor_sync(0xffffffffu, s0, 2);
        s1 += __shfl_xor_sync(0xffffffffu, s1, 1);
        s1 += __shfl_xor_sync(0xffffffffu, s1, 2);
        l0 = l0 * c0 + s0;
        l1 = l1 * c1 + s1;
        #pragma unroll
        for (int nt = 0; nt < 8; nt++) {
            accO[nt][0] *= c0; accO[nt][1] *= c0;
            accO[nt][2] *= c1; accO[nt][3] *= c1;
        }
        __syncwarp();   // Ps written by this warp, read by this warp

        // ---- O += P @ V ----
        #pragma unroll
        for (int ks = 0; ks < 8; ks++) {
            int kb = ks * 8;
            uint32_t a[4];
            a[0] = Ps[r0*AP_STR + kb + lq];
            a[1] = Ps[r1*AP_STR + kb + lq];
            a[2] = Ps[r0*AP_STR + kb + 4 + lq];
            a[3] = Ps[r1*AP_STR + kb + 4 + lq];
            #pragma unroll
            for (int nt = 0; nt < 8; nt++) {
                int bc = 8*nt + lr;
                mma_tf32(accO[nt], a,
                         Vs[(kb + lq)*AV_STR + bc],
                         Vs[(kb + 4 + lq)*AV_STR + bc]);
            }
        }
        __syncthreads();   // all warps done reading Ks/Vs

        if (k0 + 64 < SSL) {   // next K/V tile
            size_t base = ((size_t)(b*SSL + k0 + 64 + krow))*DD + h*HDD;
            #pragma unroll
            for (int j = 0; j < 4; j++) {
                int c = kv + 4*j;
                float4 kf = *(const float4*)(g_kt + base + 4*c);
                *(uint4*)&Ks[krow*AK_STR + 4*c] =
                    make_uint4(f2tf32(kf.x), f2tf32(kf.y), f2tf32(kf.z), f2tf32(kf.w));
                float4 vf = *(const float4*)(g_v + base + 4*c);
                *(uint4*)&Vs[krow*AV_STR + 4*c] =
                    make_uint4(f2tf32(vf.x), f2tf32(vf.y), f2tf32(vf.z), f2tf32(vf.w));
            }
        }
        __syncthreads();   // new tile visible
    }

    // ---- epilogue: O / l ----
    {
        float li0 = 1.0f / l0, li1 = 1.0f / l1;
        size_t row0 = (size_t)(b*SSL + qt*128 + r0) * DD + h*HDD;
        size_t row1 = (size_t)(b*SSL + qt*128 + r1) * DD + h*HDD;
        #pragma unroll
        for (int nt = 0; nt < 8; nt++) {
            int col = 8*nt + 2*lq;
            *(float2*)(out + row0 + col) = make_float2(accO[nt][0]*li0, accO[nt][1]*li0);
            *(float2*)(out + row1 + col) = make_float2(accO[nt][2]*li1, accO[nt][3]*li1);
        }
    }
}

// ---------------------------------------------------------------------------
extern "C" void kernel_launch(void* const* d_in, const int* in_sizes, int n_in,
                              void* d_out, int out_size)
{
    const float* X     = (const float*)d_in[0];
    const int*   amask = (const int*)  d_in[1];
    const float* Wq    = (const float*)d_in[2];
    const float* bq    = (const float*)d_in[3];
    const float* Wk    = (const float*)d_in[4];
    const float* bk    = (const float*)d_in[5];
    float*       out   = (float*)d_out;

    cudaFuncSetAttribute(proj_tc,
                         cudaFuncAttributeMaxDynamicSharedMemorySize, PROJ_SMEM);
    cudaFuncSetAttribute(attn_tc,
                         cudaFuncAttributeMaxDynamicSharedMemorySize, SMEM_ATTN);

    proj_tc<<<dim3(DD/64, MSZ/128), 256, PROJ_SMEM>>>(X, Wq, bq, Wk, bk);
    attn_tc<<<dim3(SSL/128, HH, BB), 256, SMEM_ATTN>>>(amask, out);
}

// round 6
// speedup vs baseline: 1.5575x; 1.1075x over previous
#include <cuda_runtime.h>
#include <math.h>
#include <stdint.h>

#define BB  2
#define SSL 2048
#define DD  1024
#define HH  16
#define HDD 64
#define MSZ (BB*SSL)

// Scratch (allocation-free rule: device globals)
__device__ float g_q[MSZ*DD];
__device__ float g_kt[MSZ*DD];   // softplus(K)
__device__ float g_v[MSZ*DD];    // Q + K

// ---------------------------------------------------------------------------
// tf32 helpers
// ---------------------------------------------------------------------------
__device__ __forceinline__ uint32_t f2tf32(float x) {
    uint32_t r;
    asm("cvt.rna.tf32.f32 %0, %1;" : "=r"(r) : "f"(x));
    return r;
}

__device__ __forceinline__ void mma_tf32(float c[4], const uint32_t a[4],
                                         uint32_t b0, uint32_t b1) {
    asm volatile(
        "mma.sync.aligned.m16n8k8.row.col.f32.tf32.tf32.f32 "
        "{%0,%1,%2,%3}, {%4,%5,%6,%7}, {%8,%9}, {%0,%1,%2,%3};"
        : "+f"(c[0]), "+f"(c[1]), "+f"(c[2]), "+f"(c[3])
        : "r"(a[0]), "r"(a[1]), "r"(a[2]), "r"(a[3]), "r"(b0), "r"(b1));
}

__device__ __forceinline__ float softplus_f(float x) {
    return (x > 15.0f) ? x : log1pf(__expf(x));
}

// ---------------------------------------------------------------------------
// Fused projection (unchanged from round 5): Q and K on the same X tile,
// epilogue writes g_q, g_kt=softplus(K), g_v=Q+K.
// ---------------------------------------------------------------------------
#define XS_STR 36
#define WS_STR 72
#define XS_BUF (128*XS_STR)
#define WS_BUF (32*WS_STR)
#define PROJ_SMEM ((2*XS_BUF + 4*WS_BUF)*4)

__global__ void __launch_bounds__(256, 2) proj_tc(
    const float* __restrict__ X,
    const float* __restrict__ Wq, const float* __restrict__ bq,
    const float* __restrict__ Wk, const float* __restrict__ bk)
{
    extern __shared__ uint32_t psm[];
    uint32_t* XsB  = psm;
    uint32_t* WqsB = psm + 2*XS_BUF;
    uint32_t* WksB = WqsB + 2*WS_BUF;

    const int m0 = blockIdx.y * 128;
    const int n0 = blockIdx.x * 64;
    const int t    = threadIdx.x;
    const int warp = t >> 5;
    const int lane = t & 31;
    const int lq   = lane & 3;
    const int lr   = lane >> 2;
    const int wm = (warp >> 1) * 32;
    const int wn = (warp & 1) * 32;

    const int xr = t >> 1;
    const int xcb = (t & 1) * 4;
    const int wr = t >> 3;
    const int wcb = t & 7;

    float accq[2][4][4] = {};
    float acck[2][4][4] = {};

    {
        const float* xp = X + (size_t)(m0 + xr) * DD;
        #pragma unroll
        for (int j = 0; j < 4; j++) {
            int c = xcb + j;
            float4 f = *(const float4*)(xp + 4*c);
            *(uint4*)&XsB[xr*XS_STR + 4*c] =
                make_uint4(f2tf32(f.x), f2tf32(f.y), f2tf32(f.z), f2tf32(f.w));
        }
        const float* wqp = Wq + (size_t)wr * DD + n0;
        const float* wkp = Wk + (size_t)wr * DD + n0;
        #pragma unroll
        for (int j = 0; j < 2; j++) {
            int c = wcb + 8*j;
            float4 fq = *(const float4*)(wqp + 4*c);
            *(uint4*)&WqsB[wr*WS_STR + 4*c] =
                make_uint4(f2tf32(fq.x), f2tf32(fq.y), f2tf32(fq.z), f2tf32(fq.w));
            float4 fk = *(const float4*)(wkp + 4*c);
            *(uint4*)&WksB[wr*WS_STR + 4*c] =
                make_uint4(f2tf32(fk.x), f2tf32(fk.y), f2tf32(fk.z), f2tf32(fk.w));
        }
    }
    __syncthreads();

    for (int k0 = 0; k0 < DD; k0 += 32) {
        const int buf = (k0 >> 5) & 1;
        uint32_t* Xs  = XsB  + buf*XS_BUF;
        uint32_t* Wqs = WqsB + buf*WS_BUF;
        uint32_t* Wks = WksB + buf*WS_BUF;
        const bool more = (k0 + 32) < DD;

        float4 xst[4], wqst[2], wkst[2];
        if (more) {
            const float* xp = X + (size_t)(m0 + xr) * DD + k0 + 32;
            #pragma unroll
            for (int j = 0; j < 4; j++)
                xst[j] = *(const float4*)(xp + 4*(xcb + j));
            const float* wqp = Wq + (size_t)(k0 + 32 + wr) * DD + n0;
            const float* wkp = Wk + (size_t)(k0 + 32 + wr) * DD + n0;
            #pragma unroll
            for (int j = 0; j < 2; j++) {
                wqst[j] = *(const float4*)(wqp + 4*(wcb + 8*j));
                wkst[j] = *(const float4*)(wkp + 4*(wcb + 8*j));
            }
        }

        #pragma unroll
        for (int ks = 0; ks < 4; ks++) {
            int kb = ks * 8;
            uint32_t a[2][4];
            #pragma unroll
            for (int mt = 0; mt < 2; mt++) {
                int ar = wm + 16*mt + lr;
                a[mt][0] = Xs[ar*XS_STR + kb + lq];
                a[mt][1] = Xs[(ar+8)*XS_STR + kb + lq];
                a[mt][2] = Xs[ar*XS_STR + kb + lq + 4];
                a[mt][3] = Xs[(ar+8)*XS_STR + kb + lq + 4];
            }
            #pragma unroll
            for (int nt = 0; nt < 4; nt++) {
                int bc = wn + 8*nt + lr;
                uint32_t q0 = Wqs[(kb + lq)*WS_STR + bc];
                uint32_t q1 = Wqs[(kb + 4 + lq)*WS_STR + bc];
                uint32_t k0r = Wks[(kb + lq)*WS_STR + bc];
                uint32_t k1r = Wks[(kb + 4 + lq)*WS_STR + bc];
                #pragma unroll
                for (int mt = 0; mt < 2; mt++) {
                    mma_tf32(accq[mt][nt], a[mt], q0, q1);
                    mma_tf32(acck[mt][nt], a[mt], k0r, k1r);
                }
            }
        }

        if (more) {
            uint32_t* Xn  = XsB  + (buf^1)*XS_BUF;
            uint32_t* Wqn = WqsB + (buf^1)*WS_BUF;
            uint32_t* Wkn = WksB + (buf^1)*WS_BUF;
            #pragma unroll
            for (int j = 0; j < 4; j++) {
                float4 f = xst[j];
                *(uint4*)&Xn[xr*XS_STR + 4*(xcb + j)] =
                    make_uint4(f2tf32(f.x), f2tf32(f.y), f2tf32(f.z), f2tf32(f.w));
            }
            #pragma unroll
            for (int j = 0; j < 2; j++) {
                float4 fq = wqst[j];
                *(uint4*)&Wqn[wr*WS_STR + 4*(wcb + 8*j)] =
                    make_uint4(f2tf32(fq.x), f2tf32(fq.y), f2tf32(fq.z), f2tf32(fq.w));
                float4 fk = wkst[j];
                *(uint4*)&Wkn[wr*WS_STR + 4*(wcb + 8*j)] =
                    make_uint4(f2tf32(fk.x), f2tf32(fk.y), f2tf32(fk.z), f2tf32(fk.w));
            }
        }
        __syncthreads();
    }

    #pragma unroll
    for (int nt = 0; nt < 4; nt++) {
        int c = n0 + wn + 8*nt + 2*lq;
        float bqx = bq[c], bqy = bq[c+1];
        float bkx = bk[c], bky = bk[c+1];
        #pragma unroll
        for (int mt = 0; mt < 2; mt++) {
            #pragma unroll
            for (int half = 0; half < 2; half++) {
                int r = m0 + wm + 16*mt + lr + 8*half;
                float qx = accq[mt][nt][2*half+0] + bqx;
                float qy = accq[mt][nt][2*half+1] + bqy;
                float kx = acck[mt][nt][2*half+0] + bkx;
                float ky = acck[mt][nt][2*half+1] + bky;
                size_t off = (size_t)r * DD + c;
                *(float2*)(g_q  + off) = make_float2(qx, qy);
                *(float2*)(g_kt + off) = make_float2(softplus_f(kx), softplus_f(ky));
                *(float2*)(g_v  + off) = make_float2(qx + kx, qy + ky);
            }
        }
    }
}

// ---------------------------------------------------------------------------
// Flash attention v3: Q-tile 256, 256 threads (8 warps), warp tile 32x64
// (2 m-frags -> B-fragments reused 2x). Double-buffered K/V smem with
// register prefetch; ONE __syncthreads per key tile. Register-resident
// online softmax. Query-axis mask -> row -10000 (uniform softmax).
// ---------------------------------------------------------------------------
#define AQ_STR 68
#define AK_STR 68
#define AV_STR 72
#define AP_STR 68
#define KBUF (64*AK_STR)
#define VBUF (64*AV_STR)
#define SMEM_ATTN ((256*AQ_STR + 2*KBUF + 2*VBUF + 256*AP_STR)*4)

__global__ void __launch_bounds__(256, 1) attn_tc(
    const int* __restrict__ amask, float* __restrict__ out)
{
    extern __shared__ uint32_t smu[];
    uint32_t* Qs  = smu;                    // [256][AQ_STR]
    uint32_t* KsB = Qs  + 256*AQ_STR;       // [2][64][AK_STR]
    uint32_t* VsB = KsB + 2*KBUF;           // [2][64][AV_STR]
    uint32_t* Ps  = VsB + 2*VBUF;           // [256][AP_STR]

    const int qt = blockIdx.x, h = blockIdx.y, b = blockIdx.z;
    const int t    = threadIdx.x;
    const int warp = t >> 5;
    const int lane = t & 31;
    const int lq   = lane & 3;
    const int lr   = lane >> 2;
    const int wm   = warp * 32;             // warp's 32 query rows
    const int krow = t >> 2, kv = t & 3;    // K/V loader: 64 rows x 4 threads

    {   // Q tile: 256 rows, 1 row/thread, tf32 with 1/8 folded
        const float* qp = g_q + ((size_t)(b*SSL + qt*256 + t))*DD + h*HDD;
        #pragma unroll
        for (int c = 0; c < 16; c++) {
            float4 f = *(const float4*)(qp + 4*c);
            *(uint4*)&Qs[t*AQ_STR + 4*c] =
                make_uint4(f2tf32(f.x*0.125f), f2tf32(f.y*0.125f),
                           f2tf32(f.z*0.125f), f2tf32(f.w*0.125f));
        }
    }
    {   // K/V tile 0 -> buffer 0
        size_t base = ((size_t)(b*SSL + krow))*DD + h*HDD;
        #pragma unroll
        for (int j = 0; j < 4; j++) {
            int c = kv + 4*j;
            float4 kf = *(const float4*)(g_kt + base + 4*c);
            *(uint4*)&KsB[krow*AK_STR + 4*c] =
                make_uint4(f2tf32(kf.x), f2tf32(kf.y), f2tf32(kf.z), f2tf32(kf.w));
            float4 vf = *(const float4*)(g_v + base + 4*c);
            *(uint4*)&VsB[krow*AV_STR + 4*c] =
                make_uint4(f2tf32(vf.x), f2tf32(vf.y), f2tf32(vf.z), f2tf32(vf.w));
        }
    }
    // mask flags for this thread's 4 rows (wm+lr, +8, +16, +24)
    bool mflag[2][2];
    #pragma unroll
    for (int mt = 0; mt < 2; mt++) {
        mflag[mt][0] = (amask[b*SSL + qt*256 + wm + 16*mt + lr] == 0);
        mflag[mt][1] = (amask[b*SSL + qt*256 + wm + 16*mt + 8 + lr] == 0);
    }

    float mm[2][2] = {{-1e30f,-1e30f},{-1e30f,-1e30f}};
    float ll[2][2] = {{0.0f,0.0f},{0.0f,0.0f}};
    float accO[2][8][4] = {};
    __syncthreads();

    for (int it = 0; it < SSL/64; it++) {
        const int buf = it & 1;
        uint32_t* Ks = KsB + buf*KBUF;
        uint32_t* Vs = VsB + buf*VBUF;
        const bool more = (it + 1) < SSL/64;

        // prefetch next K/V tile into registers (consumed after softmax)
        float4 pk[4], pv[4];
        if (more) {
            size_t base = ((size_t)(b*SSL + (it+1)*64 + krow))*DD + h*HDD;
            #pragma unroll
            for (int j = 0; j < 4; j++) {
                int c = kv + 4*j;
                pk[j] = *(const float4*)(g_kt + base + 4*c);
                pv[j] = *(const float4*)(g_v  + base + 4*c);
            }
        }

        // ---- S = (Q/8) @ K^T : warp computes 32x64 ----
        float accS[2][8][4] = {};
        #pragma unroll
        for (int ks = 0; ks < 8; ks++) {
            int kb = ks * 8;
            uint32_t a[2][4];
            #pragma unroll
            for (int mt = 0; mt < 2; mt++) {
                int ar = wm + 16*mt + lr;
                a[mt][0] = Qs[ar*AQ_STR + kb + lq];
                a[mt][1] = Qs[(ar+8)*AQ_STR + kb + lq];
                a[mt][2] = Qs[ar*AQ_STR + kb + 4 + lq];
                a[mt][3] = Qs[(ar+8)*AQ_STR + kb + 4 + lq];
            }
            #pragma unroll
            for (int nt = 0; nt < 8; nt++) {
                int key0 = 8*nt + lr;
                uint32_t b0 = Ks[key0*AK_STR + kb + lq];
                uint32_t b1 = Ks[key0*AK_STR + kb + 4 + lq];
                mma_tf32(accS[0][nt], a[0], b0, b1);
                mma_tf32(accS[1][nt], a[1], b0, b1);
            }
        }

        // ---- online softmax (registers), P -> smem (tf32) ----
        #pragma unroll
        for (int mt = 0; mt < 2; mt++) {
            const bool mA = mflag[mt][0], mB = mflag[mt][1];
            float mx0 = -1e30f, mx1 = -1e30f;
            #pragma unroll
            for (int nt = 0; nt < 8; nt++) {
                mx0 = fmaxf(mx0, fmaxf(accS[mt][nt][0], accS[mt][nt][1]));
                mx1 = fmaxf(mx1, fmaxf(accS[mt][nt][2], accS[mt][nt][3]));
            }
            if (mA) mx0 = -10000.0f;
            if (mB) mx1 = -10000.0f;
            mx0 = fmaxf(mx0, __shfl_xor_sync(0xffffffffu, mx0, 1));
            mx0 = fmaxf(mx0, __shfl_xor_sync(0xffffffffu, mx0, 2));
            mx1 = fmaxf(mx1, __shfl_xor_sync(0xffffffffu, mx1, 1));
            mx1 = fmaxf(mx1, __shfl_xor_sync(0xffffffffu, mx1, 2));
            float mn0 = fmaxf(mm[mt][0], mx0), mn1 = fmaxf(mm[mt][1], mx1);
            float c0 = __expf(mm[mt][0] - mn0), c1 = __expf(mm[mt][1] - mn1);
            mm[mt][0] = mn0; mm[mt][1] = mn1;
            float s0 = 0.0f, s1 = 0.0f;
            int ra = wm + 16*mt + lr, rb = ra + 8;
            #pragma unroll
            for (int nt = 0; nt < 8; nt++) {
                float p00 = __expf((mA ? -10000.0f : accS[mt][nt][0]) - mn0);
                float p01 = __expf((mA ? -10000.0f : accS[mt][nt][1]) - mn0);
                float p10 = __expf((mB ? -10000.0f : accS[mt][nt][2]) - mn1);
                float p11 = __expf((mB ? -10000.0f : accS[mt][nt][3]) - mn1);
                s0 += p00 + p01;
                s1 += p10 + p11;
                *(uint2*)&Ps[ra*AP_STR + 8*nt + 2*lq] = make_uint2(f2tf32(p00), f2tf32(p01));
                *(uint2*)&Ps[rb*AP_STR + 8*nt + 2*lq] = make_uint2(f2tf32(p10), f2tf32(p11));
            }
            s0 += __shfl_xor_sync(0xffffffffu, s0, 1);
            s0 += __shfl_xor_sync(0xffffffffu, s0, 2);
            s1 += __shfl_xor_sync(0xffffffffu, s1, 1);
            s1 += __shfl_xor_sync(0xffffffffu, s1, 2);
            ll[mt][0] = ll[mt][0] * c0 + s0;
            ll[mt][1] = ll[mt][1] * c1 + s1;
            #pragma unroll
            for (int nt = 0; nt < 8; nt++) {
                accO[mt][nt][0] *= c0; accO[mt][nt][1] *= c0;
                accO[mt][nt][2] *= c1; accO[mt][nt][3] *= c1;
            }
        }
        __syncwarp();   // Ps written/read within warp

        // ---- stash prefetched K/V into the other buffer ----
        if (more) {
            uint32_t* Kn = KsB + (buf^1)*KBUF;
            uint32_t* Vn = VsB + (buf^1)*VBUF;
            #pragma unroll
            for (int j = 0; j < 4; j++) {
                int c = kv + 4*j;
                *(uint4*)&Kn[krow*AK_STR + 4*c] =
                    make_uint4(f2tf32(pk[j].x), f2tf32(pk[j].y),
                               f2tf32(pk[j].z), f2tf32(pk[j].w));
                *(uint4*)&Vn[krow*AV_STR + 4*c] =
                    make_uint4(f2tf32(pv[j].x), f2tf32(pv[j].y),
                               f2tf32(pv[j].z), f2tf32(pv[j].w));
            }
        }

        // ---- O += P @ V ----
        #pragma unroll
        for (int ks = 0; ks < 8; ks++) {
            int kb = ks * 8;
            uint32_t a[2][4];
            #pragma unroll
            for (int mt = 0; mt < 2; mt++) {
                int ar = wm + 16*mt + lr;
                a[mt][0] = Ps[ar*AP_STR + kb + lq];
                a[mt][1] = Ps[(ar+8)*AP_STR + kb + lq];
                a[mt][2] = Ps[ar*AP_STR + kb + 4 + lq];
                a[mt][3] = Ps[(ar+8)*AP_STR + kb + 4 + lq];
            }
            #pragma unroll
            for (int nt = 0; nt < 8; nt++) {
                int bc = 8*nt + lr;
                uint32_t b0 = Vs[(kb + lq)*AV_STR + bc];
                uint32_t b1 = Vs[(kb + 4 + lq)*AV_STR + bc];
                mma_tf32(accO[0][nt], a[0], b0, b1);
                mma_tf32(accO[1][nt], a[1], b0, b1);
            }
        }
        __syncthreads();   // tile done: buf consumed by all, buf^1 fully written
    }

    // ---- epilogue: O / l ----
    #pragma unroll
    for (int mt = 0; mt < 2; mt++) {
        int ra = wm + 16*mt + lr, rb = ra + 8;
        float li0 = 1.0f / ll[mt][0], li1 = 1.0f / ll[mt][1];
        size_t row0 = (size_t)(b*SSL + qt*256 + ra) * DD + h*HDD;
        size_t row1 = (size_t)(b*SSL + qt*256 + rb) * DD + h*HDD;
        #pragma unroll
        for (int nt = 0; nt < 8; nt++) {
            int col = 8*nt + 2*lq;
            *(float2*)(out + row0 + col) =
                make_float2(accO[mt][nt][0]*li0, accO[mt][nt][1]*li0);
            *(float2*)(out + row1 + col) =
                make_float2(accO[mt][nt][2]*li1, accO[mt][nt][3]*li1);
        }
    }
}

// ---------------------------------------------------------------------------
extern "C" void kernel_launch(void* const* d_in, const int* in_sizes, int n_in,
                              void* d_out, int out_size)
{
    const float* X     = (const float*)d_in[0];
    const int*   amask = (const int*)  d_in[1];
    const float* Wq    = (const float*)d_in[2];
    const float* bq    = (const float*)d_in[3];
    const float* Wk    = (const float*)d_in[4];
    const float* bk    = (const float*)d_in[5];
    float*       out   = (float*)d_out;

    cudaFuncSetAttribute(proj_tc,
                         cudaFuncAttributeMaxDynamicSharedMemorySize, PROJ_SMEM);
    cudaFuncSetAttribute(attn_tc,
                         cudaFuncAttributeMaxDynamicSharedMemorySize, SMEM_ATTN);

    proj_tc<<<dim3(DD/64, MSZ/128), 256, PROJ_SMEM>>>(X, Wq, bq, Wk, bk);
    attn_tc<<<dim3(SSL/256, HH, BB), 256, SMEM_ATTN>>>(amask, out);
}